// round 12
// baseline (speedup 1.0000x reference)
#include <cuda_runtime.h>
#include <cuda_fp16.h>
#include <mma.h>
#include <cstdint>

using namespace nvcuda;

namespace cfg {
constexpr int DM  = 1024;
constexpr int NH  = 16;
constexpr int HD  = 64;
constexpr int B   = 4;
constexpr int LQ  = 512;
constexpr int LKV = 2048;
constexpr int LDH = 72;    // half leading dim (64+8): 144B rows, LDSM conflict-free
constexpr int LDE = 132;   // gemm epilogue fp32 staging leading dim
}

// -------- half scratch (inputs pre-converted once) -------------------------
__device__ __half g_xq [(size_t)cfg::B * cfg::LQ  * cfg::DM];
__device__ __half g_xkv[(size_t)cfg::B * cfg::LKV * cfg::DM];
__device__ __half g_wq [(size_t)cfg::DM * cfg::DM];
__device__ __half g_wk [(size_t)cfg::DM * cfg::DM];
__device__ __half g_wv [(size_t)cfg::DM * cfg::DM];
__device__ __half g_wo [(size_t)cfg::DM * cfg::DM];
__device__ __half g_Qh [(size_t)cfg::B * cfg::NH * cfg::LQ  * cfg::HD];
__device__ __half g_Kh [(size_t)cfg::B * cfg::NH * cfg::LKV * cfg::HD];
__device__ __half g_Vh [(size_t)cfg::B * cfg::NH * cfg::LKV * cfg::HD];
__device__ __half g_ctx[(size_t)cfg::B * cfg::LQ * cfg::DM];

__device__ __forceinline__ uint32_t smem_u32(const void* p) {
    uint32_t a;
    asm("{ .reg .u64 t; cvta.to.shared.u64 t, %1; cvt.u32.u64 %0, t; }"
        : "=r"(a) : "l"(p));
    return a;
}
#define CP_ASYNC16(dst_u32, src_ptr) \
    asm volatile("cp.async.cg.shared.global [%0], [%1], 16;" \
                 :: "r"(dst_u32), "l"(src_ptr) : "memory")
#define CP_ASYNC_COMMIT() asm volatile("cp.async.commit_group;" ::: "memory")
#define CP_ASYNC_WAIT0()  asm volatile("cp.async.wait_group 0;" ::: "memory")
#define CP_ASYNC_WAIT1()  asm volatile("cp.async.wait_group 1;" ::: "memory")

__device__ __forceinline__ void ldsm_x4(uint32_t& r0, uint32_t& r1,
                                        uint32_t& r2, uint32_t& r3, uint32_t addr) {
    asm volatile("ldmatrix.sync.aligned.m8n8.x4.shared.b16 {%0,%1,%2,%3}, [%4];"
                 : "=r"(r0), "=r"(r1), "=r"(r2), "=r"(r3) : "r"(addr));
}
__device__ __forceinline__ void ldsm_x4_t(uint32_t& r0, uint32_t& r1,
                                          uint32_t& r2, uint32_t& r3, uint32_t addr) {
    asm volatile("ldmatrix.sync.aligned.m8n8.x4.trans.shared.b16 {%0,%1,%2,%3}, [%4];"
                 : "=r"(r0), "=r"(r1), "=r"(r2), "=r"(r3) : "r"(addr));
}
__device__ __forceinline__ void mma16816(float* d, const uint32_t* a,
                                         uint32_t b0, uint32_t b1) {
    asm volatile(
        "mma.sync.aligned.m16n8k16.row.col.f32.f16.f16.f32 "
        "{%0,%1,%2,%3}, {%4,%5,%6,%7}, {%8,%9}, {%0,%1,%2,%3};"
        : "+f"(d[0]), "+f"(d[1]), "+f"(d[2]), "+f"(d[3])
        : "r"(a[0]), "r"(a[1]), "r"(a[2]), "r"(a[3]), "r"(b0), "r"(b1));
}

// ---------------------------------------------------------------------------
// fp32 -> fp16 bulk convert, all six tensors in one launch.
// ---------------------------------------------------------------------------
struct F2HArgs {
    const float* src[6];
    __half*      dst[6];
    int          n[6];
};
__global__ void f2h_all(F2HArgs p)
{
#pragma unroll
    for (int seg = 0; seg < 6; seg++) {
        const float* a = p.src[seg];
        __half*      b = p.dst[seg];
        const int    n = p.n[seg];
        int i = (blockIdx.x * blockDim.x + threadIdx.x) * 4;
        int stride = gridDim.x * blockDim.x * 4;
        for (; i < n; i += stride) {
            float4 v = *reinterpret_cast<const float4*>(a + i);
            __half2 h0 = __floats2half2_rn(v.x, v.y);
            __half2 h1 = __floats2half2_rn(v.z, v.w);
            uint2 u;
            u.x = *reinterpret_cast<uint32_t*>(&h0);
            u.y = *reinterpret_cast<uint32_t*>(&h1);
            *reinterpret_cast<uint2*>(b + i) = u;
        }
    }
}

// ---------------------------------------------------------------------------
// Shared GEMM body: Y = X @ W^T + bias, 128x128 tile, 8 warps (warp 32x64),
// K-chunk 64, THREE-stage cp.async ring (was 2): a full chunk of LDG latency
// stays hidden behind the MMA block.
// ---------------------------------------------------------------------------
template <bool OUT_HALF>
__device__ __forceinline__ void gemm_body(
    const __half* __restrict__ X, const __half* __restrict__ W,
    const float* __restrict__ bias, void* __restrict__ Yv,
    int m0, int n0, int seq, float scale, __half* smh)
{
    using namespace cfg;
    constexpr int KC = 64, NCH = DM / KC;   // 16 chunks
    constexpr int BUF = 128 * LDH;          // halves per operand buffer
    // layout: [X0|W0|X1|W1|X2|W2]
    __half* bx[3] = { smh,           smh + 2 * BUF, smh + 4 * BUF };
    __half* bw[3] = { smh + BUF,     smh + 3 * BUF, smh + 5 * BUF };
    const uint32_t bxa[3] = { smem_u32(bx[0]), smem_u32(bx[1]), smem_u32(bx[2]) };
    const uint32_t bwa[3] = { smem_u32(bw[0]), smem_u32(bw[1]), smem_u32(bw[2]) };

    const int tid  = threadIdx.x;
    const int warp = tid >> 5;
    const int wr   = warp >> 1;
    const int wc   = warp & 1;

    wmma::fragment<wmma::accumulator, 16, 16, 16, float> acc[2][4];
#pragma unroll
    for (int i = 0; i < 2; i++)
#pragma unroll
        for (int j = 0; j < 4; j++) wmma::fill_fragment(acc[i][j], 0.0f);

    auto stage = [&](int s, int k0) {
#pragma unroll
        for (int i = 0; i < 4; i++) {
            int f = i * 256 + tid;
            int r = f >> 3, c8 = (f & 7) * 8;
            CP_ASYNC16(bxa[s] + (uint32_t)(r * LDH + c8) * 2,
                       X + (size_t)(m0 + r) * DM + k0 + c8);
            CP_ASYNC16(bwa[s] + (uint32_t)(r * LDH + c8) * 2,
                       W + (size_t)(n0 + r) * DM + k0 + c8);
        }
        CP_ASYNC_COMMIT();
    };

    stage(0, 0);
    stage(1, KC);
    for (int kc = 0; kc < NCH; kc++) {
        const int s = kc % 3;
        if (kc < NCH - 1) CP_ASYNC_WAIT1();   // chunks kc..kc+1 staged; kc done
        else              CP_ASYNC_WAIT0();
        __syncthreads();                       // all warps done with buf (kc+2)%3's prior use
        if (kc + 2 < NCH) stage((kc + 2) % 3, (kc + 2) * KC);
#pragma unroll
        for (int kk = 0; kk < KC; kk += 16) {
            wmma::fragment<wmma::matrix_a, 16, 16, 16, __half, wmma::row_major> a[2];
#pragma unroll
            for (int i = 0; i < 2; i++)
                wmma::load_matrix_sync(a[i], bx[s] + (wr * 32 + i * 16) * LDH + kk, LDH);
#pragma unroll
            for (int j = 0; j < 4; j++) {
                wmma::fragment<wmma::matrix_b, 16, 16, 16, __half, wmma::col_major> bf;
                wmma::load_matrix_sync(bf, bw[s] + (wc * 64 + j * 16) * LDH + kk, LDH);
#pragma unroll
                for (int i = 0; i < 2; i++)
                    wmma::mma_sync(acc[i][j], a[i], bf, acc[i][j]);
            }
        }
    }
    __syncthreads();   // last chunk's buffer aliases the epilogue staging below

    float* stf = reinterpret_cast<float*>(smh);   // 128*LDE*4 = 67584 <= 110592
#pragma unroll
    for (int i = 0; i < 2; i++)
#pragma unroll
        for (int j = 0; j < 4; j++)
            wmma::store_matrix_sync(stf + (wr * 32 + i * 16) * LDE + wc * 64 + j * 16,
                                    acc[i][j], LDE, wmma::mem_row_major);
    __syncthreads();
#pragma unroll
    for (int i = 0; i < 16; i++) {
        int f = i * 256 + tid;
        int r = f >> 5, c = (f & 31) << 2;
        float4 v  = *reinterpret_cast<float4*>(stf + r * LDE + c);
        float4 bv = *reinterpret_cast<const float4*>(bias + n0 + c);
        v.x += bv.x; v.y += bv.y; v.z += bv.z; v.w += bv.w;
        if (!OUT_HALF) {
            *reinterpret_cast<float4*>((float*)Yv + (size_t)(m0 + r) * DM + n0 + c) = v;
        } else {
            __half2 h0 = __floats2half2_rn(v.x * scale, v.y * scale);
            __half2 h1 = __floats2half2_rn(v.z * scale, v.w * scale);
            uint2 u;
            u.x = *reinterpret_cast<uint32_t*>(&h0);
            u.y = *reinterpret_cast<uint32_t*>(&h1);
            int h    = (n0 + c) >> 6;
            int bidx = (m0 + r) / seq;
            int l    = (m0 + r) % seq;
            *reinterpret_cast<uint2*>((__half*)Yv +
                (((size_t)(bidx * NH + h) * seq + l) << 6) + (c & 63)) = u;
        }
    }
}

__global__ __launch_bounds__(256, 2) void gemm_qkv(
    const __half* __restrict__ xq, const __half* __restrict__ xkv,
    const __half* __restrict__ wq, const __half* __restrict__ wk,
    const __half* __restrict__ wv,
    const float* __restrict__ bq, const float* __restrict__ bk,
    const float* __restrict__ bv,
    __half* __restrict__ Qh, __half* __restrict__ Kh, __half* __restrict__ Vh)
{
    using namespace cfg;
    extern __shared__ __half smh[];
    const int ty = blockIdx.y;
    const int n0 = blockIdx.x * 128;

    const __half *X, *W; const float* bias; __half* Y;
    int seq, m0; float scale;
    if (ty < 16)      { X = xq;  W = wq; bias = bq; Y = Qh; seq = LQ;  scale = 0.125f; m0 = ty * 128; }
    else if (ty < 80) { X = xkv; W = wk; bias = bk; Y = Kh; seq = LKV; scale = 1.0f;   m0 = (ty - 16) * 128; }
    else              { X = xkv; W = wv; bias = bv; Y = Vh; seq = LKV; scale = 1.0f;   m0 = (ty - 80) * 128; }

    gemm_body<true>(X, W, bias, Y, m0, n0, seq, scale, smh);
}

__global__ __launch_bounds__(256, 2) void gemm_o(
    const __half* __restrict__ X, const __half* __restrict__ W,
    const float* __restrict__ bias, float* __restrict__ Y)
{
    using namespace cfg;
    extern __shared__ __half smh[];
    gemm_body<false>(X, W, bias, Y, blockIdx.y * 128, blockIdx.x * 128,
                     0, 1.0f, smh);
}

// ---------------------------------------------------------------------------
// Attention v3: register-resident softmax (unchanged math), KV chunk 128 rows
// per stage processed as two 64-key halves -> HALF the __syncthreads (16 vs 32)
// and longer uninterrupted MMA runs. Double-buffered cp.async as before.
// ---------------------------------------------------------------------------
__global__ __launch_bounds__(256, 2) void attn_h(
    const __half* __restrict__ Qg, const __half* __restrict__ Kg,
    const __half* __restrict__ Vg, __half* __restrict__ ctx)
{
    using namespace cfg;
    extern __shared__ char smb[];
    // sQ 18432 | K0 18432 | K1 18432 | V0 18432 | V1 18432  (128-row K/V bufs)
    __half* sQ = (__half*)(smb);
    const uint32_t sQa = smem_u32(sQ);
    const uint32_t sKa[2] = { smem_u32(smb + 18432), smem_u32(smb + 36864) };
    const uint32_t sVa[2] = { smem_u32(smb + 55296), smem_u32(smb + 73728) };

    const int tid  = threadIdx.x;
    const int warp = tid >> 5;
    const int lane = tid & 31;
    const int bh   = blockIdx.y;
    const int q0   = blockIdx.x * 128;

    const __half* Q = Qg + (size_t)bh * LQ  * HD;
    const __half* K = Kg + (size_t)bh * LKV * HD;
    const __half* V = Vg + (size_t)bh * LKV * HD;

    // ldmatrix lane geometry
    const int grp = lane >> 3, li = lane & 7;
    const int krow = ((grp >> 1) << 3) + li, kcol = (grp & 1) << 3;  // K (b-frags)
    const int vrow = ((grp & 1) << 3) + li, vcol = (grp >> 1) << 3;  // V (.trans), Q (a-frags)

    auto stage_kv = [&](int s, int kc) {   // 128 rows of K and V
#pragma unroll
        for (int i = 0; i < 4; i++) {
            int f = i * 256 + tid;
            int r = f >> 3, c8 = (f & 7) * 8;
            CP_ASYNC16(sKa[s] + (uint32_t)(r * LDH + c8) * 2,
                       K + (size_t)(kc * 128 + r) * HD + c8);
            CP_ASYNC16(sVa[s] + (uint32_t)(r * LDH + c8) * 2,
                       V + (size_t)(kc * 128 + r) * HD + c8);
        }
        CP_ASYNC_COMMIT();
    };

    // Prologue: Q tile + KV chunk 0 (single commit group).
#pragma unroll
    for (int i = 0; i < 4; i++) {
        int f = i * 256 + tid;
        int r = f >> 3, c8 = (f & 7) * 8;
        CP_ASYNC16(sQa + (uint32_t)(r * LDH + c8) * 2,
                   Q + (size_t)(q0 + r) * HD + c8);
    }
    stage_kv(0, 0);

    uint32_t qa[4][4];
    float oacc[8][4];
#pragma unroll
    for (int j = 0; j < 8; j++)
#pragma unroll
        for (int t = 0; t < 4; t++) oacc[j][t] = 0.0f;
    float rs0 = 0.0f, rs1 = 0.0f;

    constexpr int NCHUNK = LKV / 128;   // 16
    for (int kc = 0; kc < NCHUNK; kc++) {
        const int s = kc & 1;
        if (kc + 1 < NCHUNK) { stage_kv(1 - s, kc + 1); CP_ASYNC_WAIT1(); }
        else                 { CP_ASYNC_WAIT0(); }
        __syncthreads();

        if (kc == 0) {   // load Q a-frags once (reused for all chunks)
#pragma unroll
            for (int ks = 0; ks < 4; ks++)
                ldsm_x4(qa[ks][0], qa[ks][1], qa[ks][2], qa[ks][3],
                        sQa + (uint32_t)((warp * 16 + vrow) * LDH + ks * 16 + vcol) * 2);
        }

#pragma unroll
        for (int h = 0; h < 2; h++) {        // two 64-key halves of the chunk
            const uint32_t kbase = sKa[s] + (uint32_t)(h * 64 * LDH) * 2;
            const uint32_t vbase = sVa[s] + (uint32_t)(h * 64 * LDH) * 2;

            // ---- S = Q @ K^T : 8 n8-tiles, fp32 acc in registers ----
            float sc[8][4];
#pragma unroll
            for (int j = 0; j < 8; j++)
#pragma unroll
                for (int t = 0; t < 4; t++) sc[j][t] = 0.0f;
#pragma unroll
            for (int ks = 0; ks < 4; ks++) {
#pragma unroll
                for (int jt = 0; jt < 4; jt++) {
                    uint32_t b0, b1, b2, b3;
                    ldsm_x4(b0, b1, b2, b3,
                            kbase + (uint32_t)((jt * 16 + krow) * LDH + ks * 16 + kcol) * 2);
                    mma16816(sc[2 * jt],     qa[ks], b0, b1);
                    mma16816(sc[2 * jt + 1], qa[ks], b2, b3);
                }
            }

            // ---- P = half(exp(S)) packed directly into PV A-frags ----
            uint32_t pa[4][4];
#pragma unroll
            for (int J = 0; J < 4; J++) {
                float* e0 = sc[2 * J];
                float* e1 = sc[2 * J + 1];
                __half2 h00 = __floats2half2_rn(__expf(e0[0]), __expf(e0[1]));
                __half2 h01 = __floats2half2_rn(__expf(e0[2]), __expf(e0[3]));
                __half2 h10 = __floats2half2_rn(__expf(e1[0]), __expf(e1[1]));
                __half2 h11 = __floats2half2_rn(__expf(e1[2]), __expf(e1[3]));
                pa[J][0] = *reinterpret_cast<uint32_t*>(&h00);
                pa[J][1] = *reinterpret_cast<uint32_t*>(&h01);
                pa[J][2] = *reinterpret_cast<uint32_t*>(&h10);
                pa[J][3] = *reinterpret_cast<uint32_t*>(&h11);
                float2 f00 = __half22float2(h00), f01 = __half22float2(h01);
                float2 f10 = __half22float2(h10), f11 = __half22float2(h11);
                rs0 += f00.x + f00.y + f10.x + f10.y;
                rs1 += f01.x + f01.y + f11.x + f11.y;
            }

            // ---- O += P @ V : 8 n8-tiles (head dim) ----
#pragma unroll
            for (int J = 0; J < 4; J++) {
#pragma unroll
                for (int dt = 0; dt < 4; dt++) {
                    uint32_t b0, b1, b2, b3;
                    ldsm_x4_t(b0, b1, b2, b3,
                              vbase + (uint32_t)((J * 16 + vrow) * LDH + dt * 16 + vcol) * 2);
                    mma16816(oacc[2 * dt],     pa[J], b0, b1);
                    mma16816(oacc[2 * dt + 1], pa[J], b2, b3);
                }
            }
        }
        __syncthreads();   // all warps done with buffer s before restaging
    }

    // ---- finalize row sums (quad reduce) and write normalized O ----
    rs0 += __shfl_xor_sync(0xffffffffu, rs0, 1);
    rs0 += __shfl_xor_sync(0xffffffffu, rs0, 2);
    rs1 += __shfl_xor_sync(0xffffffffu, rs1, 1);
    rs1 += __shfl_xor_sync(0xffffffffu, rs1, 2);
    const float i0 = 1.0f / rs0, i1 = 1.0f / rs1;

    const int b  = bh / NH, hh = bh % NH;
    const int r0 = q0 + warp * 16 + (lane >> 2);
    const int cb = (lane & 3) * 2;
#pragma unroll
    for (int j = 0; j < 8; j++) {
        __half2 h0 = __floats2half2_rn(oacc[j][0] * i0, oacc[j][1] * i0);
        __half2 h1 = __floats2half2_rn(oacc[j][2] * i1, oacc[j][3] * i1);
        *reinterpret_cast<__half2*>(ctx +
            (((size_t)(b * LQ + r0) * NH + hh) << 6) + 8 * j + cb) = h0;
        *reinterpret_cast<__half2*>(ctx +
            (((size_t)(b * LQ + r0 + 8) * NH + hh) << 6) + 8 * j + cb) = h1;
    }
}

// ---------------------------------------------------------------------------
extern "C" void kernel_launch(void* const* d_in, const int* in_sizes, int n_in,
                              void* d_out, int out_size)
{
    using namespace cfg;
    (void)in_sizes; (void)n_in; (void)out_size;

    const float* q  = (const float*)d_in[0];
    const float* kv = (const float*)d_in[1];
    const float* Wq = (const float*)d_in[2];
    const float* bq = (const float*)d_in[3];
    const float* Wk = (const float*)d_in[4];
    const float* bk = (const float*)d_in[5];
    const float* Wv = (const float*)d_in[6];
    const float* bv = (const float*)d_in[7];
    const float* Wo = (const float*)d_in[8];
    const float* bo = (const float*)d_in[9];
    float* out = (float*)d_out;

    void *p_xq, *p_xkv, *p_wq, *p_wk, *p_wv, *p_wo, *p_Q, *p_K, *p_V, *p_ctx;
    cudaGetSymbolAddress(&p_xq,  g_xq);
    cudaGetSymbolAddress(&p_xkv, g_xkv);
    cudaGetSymbolAddress(&p_wq,  g_wq);
    cudaGetSymbolAddress(&p_wk,  g_wk);
    cudaGetSymbolAddress(&p_wv,  g_wv);
    cudaGetSymbolAddress(&p_wo,  g_wo);
    cudaGetSymbolAddress(&p_Q,   g_Qh);
    cudaGetSymbolAddress(&p_K,   g_Kh);
    cudaGetSymbolAddress(&p_V,   g_Vh);
    cudaGetSymbolAddress(&p_ctx, g_ctx);
    __half* xq  = (__half*)p_xq;
    __half* xkv = (__half*)p_xkv;
    __half* ctx = (__half*)p_ctx;

    const int GEMM_SMEM = 6 * 128 * LDH * 2;   // 110592 B (3-stage ring)
    const int ATT_SMEM  = 92160;               // sQ + 2x(128-row K,V)
    cudaFuncSetAttribute(gemm_qkv,
                         cudaFuncAttributeMaxDynamicSharedMemorySize, GEMM_SMEM);
    cudaFuncSetAttribute(gemm_o,
                         cudaFuncAttributeMaxDynamicSharedMemorySize, GEMM_SMEM);
    cudaFuncSetAttribute(attn_h,
                         cudaFuncAttributeMaxDynamicSharedMemorySize, ATT_SMEM);

    F2HArgs fa;
    fa.src[0] = q;   fa.dst[0] = xq;             fa.n[0] = B * LQ  * DM;
    fa.src[1] = kv;  fa.dst[1] = xkv;            fa.n[1] = B * LKV * DM;
    fa.src[2] = Wq;  fa.dst[2] = (__half*)p_wq;  fa.n[2] = DM * DM;
    fa.src[3] = Wk;  fa.dst[3] = (__half*)p_wk;  fa.n[3] = DM * DM;
    fa.src[4] = Wv;  fa.dst[4] = (__half*)p_wv;  fa.n[4] = DM * DM;
    fa.src[5] = Wo;  fa.dst[5] = (__half*)p_wo;  fa.n[5] = DM * DM;
    f2h_all<<<2048, 256>>>(fa);

    const dim3 blk(256);

    gemm_qkv<<<dim3(DM / 128, 144), blk, GEMM_SMEM>>>(
        xq, xkv, (__half*)p_wq, (__half*)p_wk, (__half*)p_wv,
        bq, bk, bv, (__half*)p_Q, (__half*)p_K, (__half*)p_V);

    attn_h<<<dim3(LQ / 128, B * NH), blk, ATT_SMEM>>>(
        (__half*)p_Q, (__half*)p_K, (__half*)p_V, ctx);

    gemm_o<<<dim3(DM / 128, (B * LQ) / 128), blk, GEMM_SMEM>>>(
        ctx, (__half*)p_wo, bo, out);
}

// round 13
// speedup vs baseline: 1.0701x; 1.0701x over previous
#include <cuda_runtime.h>
#include <cuda_fp16.h>
#include <mma.h>
#include <cstdint>

using namespace nvcuda;

namespace cfg {
constexpr int DM  = 1024;
constexpr int NH  = 16;
constexpr int HD  = 64;
constexpr int B   = 4;
constexpr int LQ  = 512;
constexpr int LKV = 2048;
constexpr int LDH = 72;    // half leading dim (64+8): 144B rows, LDSM conflict-free
constexpr int LDE = 132;   // gemm epilogue fp32 staging leading dim
}

// -------- half scratch (inputs pre-converted once) -------------------------
__device__ __half g_xq [(size_t)cfg::B * cfg::LQ  * cfg::DM];
__device__ __half g_xkv[(size_t)cfg::B * cfg::LKV * cfg::DM];
__device__ __half g_wq [(size_t)cfg::DM * cfg::DM];
__device__ __half g_wk [(size_t)cfg::DM * cfg::DM];
__device__ __half g_wv [(size_t)cfg::DM * cfg::DM];
__device__ __half g_wo [(size_t)cfg::DM * cfg::DM];
__device__ __half g_Qh [(size_t)cfg::B * cfg::NH * cfg::LQ  * cfg::HD];
__device__ __half g_Kh [(size_t)cfg::B * cfg::NH * cfg::LKV * cfg::HD];
__device__ __half g_Vh [(size_t)cfg::B * cfg::NH * cfg::LKV * cfg::HD];
__device__ __half g_ctx[(size_t)cfg::B * cfg::LQ * cfg::DM];

__device__ __forceinline__ uint32_t smem_u32(const void* p) {
    uint32_t a;
    asm("{ .reg .u64 t; cvta.to.shared.u64 t, %1; cvt.u32.u64 %0, t; }"
        : "=r"(a) : "l"(p));
    return a;
}
#define CP_ASYNC16(dst_u32, src_ptr) \
    asm volatile("cp.async.cg.shared.global [%0], [%1], 16;" \
                 :: "r"(dst_u32), "l"(src_ptr) : "memory")
#define CP_ASYNC_COMMIT() asm volatile("cp.async.commit_group;" ::: "memory")
#define CP_ASYNC_WAIT0()  asm volatile("cp.async.wait_group 0;" ::: "memory")
#define CP_ASYNC_WAIT1()  asm volatile("cp.async.wait_group 1;" ::: "memory")

__device__ __forceinline__ void ldsm_x4(uint32_t& r0, uint32_t& r1,
                                        uint32_t& r2, uint32_t& r3, uint32_t addr) {
    asm volatile("ldmatrix.sync.aligned.m8n8.x4.shared.b16 {%0,%1,%2,%3}, [%4];"
                 : "=r"(r0), "=r"(r1), "=r"(r2), "=r"(r3) : "r"(addr));
}
__device__ __forceinline__ void ldsm_x4_t(uint32_t& r0, uint32_t& r1,
                                          uint32_t& r2, uint32_t& r3, uint32_t addr) {
    asm volatile("ldmatrix.sync.aligned.m8n8.x4.trans.shared.b16 {%0,%1,%2,%3}, [%4];"
                 : "=r"(r0), "=r"(r1), "=r"(r2), "=r"(r3) : "r"(addr));
}
__device__ __forceinline__ void mma16816(float* d, const uint32_t* a,
                                         uint32_t b0, uint32_t b1) {
    asm volatile(
        "mma.sync.aligned.m16n8k16.row.col.f32.f16.f16.f32 "
        "{%0,%1,%2,%3}, {%4,%5,%6,%7}, {%8,%9}, {%0,%1,%2,%3};"
        : "+f"(d[0]), "+f"(d[1]), "+f"(d[2]), "+f"(d[3])
        : "r"(a[0]), "r"(a[1]), "r"(a[2]), "r"(a[3]), "r"(b0), "r"(b1));
}

// ---------------------------------------------------------------------------
// fp32 -> fp16 bulk convert, all six tensors in one launch.
// ---------------------------------------------------------------------------
struct F2HArgs {
    const float* src[6];
    __half*      dst[6];
    int          n[6];
};
__global__ void f2h_all(F2HArgs p)
{
#pragma unroll
    for (int seg = 0; seg < 6; seg++) {
        const float* a = p.src[seg];
        __half*      b = p.dst[seg];
        const int    n = p.n[seg];
        int i = (blockIdx.x * blockDim.x + threadIdx.x) * 4;
        int stride = gridDim.x * blockDim.x * 4;
        for (; i < n; i += stride) {
            float4 v = *reinterpret_cast<const float4*>(a + i);
            __half2 h0 = __floats2half2_rn(v.x, v.y);
            __half2 h1 = __floats2half2_rn(v.z, v.w);
            uint2 u;
            u.x = *reinterpret_cast<uint32_t*>(&h0);
            u.y = *reinterpret_cast<uint32_t*>(&h1);
            *reinterpret_cast<uint2*>(b + i) = u;
        }
    }
}

// ---------------------------------------------------------------------------
// Shared GEMM body: Y = X @ W^T + bias, TM x 128 CTA tile, 8 warps, K-chunk
// 64, TWO-stage cp.async (R12's 3-stage ring regressed — reverted).
// TM=128: warp tile 32x64 (4x2 strips). TM=64: warp tile 32x32 (2x4 strips),
// used by gemm_o to double its grid (128 -> 256 blocks, wave fill 43% -> 86%).
// ---------------------------------------------------------------------------
template <bool OUT_HALF, int TM>
__device__ __forceinline__ void gemm_body(
    const __half* __restrict__ X, const __half* __restrict__ W,
    const float* __restrict__ bias, void* __restrict__ Yv,
    int m0, int n0, int seq, float scale, __half* smh)
{
    using namespace cfg;
    constexpr int KC  = 64, NCH = DM / KC;       // 16 chunks
    constexpr int RS  = TM / 32;                 // row strips (4 or 2)
    constexpr int CS  = 8 / RS;                  // col strips (2 or 4)
    constexpr int CW  = 128 / CS;                // cols per warp (64 or 32)
    constexpr int NB  = CW / 16;                 // b-frags per warp (4 or 2)
    constexpr int BUFX = TM  * LDH;
    constexpr int BUFW = 128 * LDH;
    // layout: [X0|W0|X1|W1]
    __half* bx[2] = { smh,                smh + BUFX + BUFW };
    __half* bw[2] = { smh + BUFX,         smh + 2 * BUFX + BUFW };
    const uint32_t bxa[2] = { smem_u32(bx[0]), smem_u32(bx[1]) };
    const uint32_t bwa[2] = { smem_u32(bw[0]), smem_u32(bw[1]) };

    const int tid  = threadIdx.x;
    const int warp = tid >> 5;
    const int wr   = warp / CS;
    const int wc   = warp % CS;

    wmma::fragment<wmma::accumulator, 16, 16, 16, float> acc[2][NB];
#pragma unroll
    for (int i = 0; i < 2; i++)
#pragma unroll
        for (int j = 0; j < NB; j++) wmma::fill_fragment(acc[i][j], 0.0f);

    // Stage one 64-deep K-chunk of X (TM rows) and W (128 rows).
    auto stage = [&](int s, int k0) {
        constexpr int ITER = (TM + 128) * 8 / 256;
#pragma unroll
        for (int i = 0; i < ITER; i++) {
            int f = i * 256 + tid;
            int r = f >> 3, c8 = (f & 7) * 8;
            if (r < TM) {
                CP_ASYNC16(bxa[s] + (uint32_t)(r * LDH + c8) * 2,
                           X + (size_t)(m0 + r) * DM + k0 + c8);
            } else {
                int rw = r - TM;
                CP_ASYNC16(bwa[s] + (uint32_t)(rw * LDH + c8) * 2,
                           W + (size_t)(n0 + rw) * DM + k0 + c8);
            }
        }
        CP_ASYNC_COMMIT();
    };

    stage(0, 0);
    for (int kc = 0; kc < NCH; kc++) {
        const int s = kc & 1;
        if (kc + 1 < NCH) { stage(1 - s, (kc + 1) * KC); CP_ASYNC_WAIT1(); }
        else              { CP_ASYNC_WAIT0(); }
        __syncthreads();
#pragma unroll
        for (int kk = 0; kk < KC; kk += 16) {
            wmma::fragment<wmma::matrix_a, 16, 16, 16, __half, wmma::row_major> a[2];
#pragma unroll
            for (int i = 0; i < 2; i++)
                wmma::load_matrix_sync(a[i], bx[s] + (wr * 32 + i * 16) * LDH + kk, LDH);
#pragma unroll
            for (int j = 0; j < NB; j++) {
                wmma::fragment<wmma::matrix_b, 16, 16, 16, __half, wmma::col_major> bf;
                wmma::load_matrix_sync(bf, bw[s] + (wc * CW + j * 16) * LDH + kk, LDH);
#pragma unroll
                for (int i = 0; i < 2; i++)
                    wmma::mma_sync(acc[i][j], a[i], bf, acc[i][j]);
            }
        }
        __syncthreads();
    }

    // Epilogue: stage TM x 128 fp32 in smem (reuse buffers), add bias, write.
    float* stf = reinterpret_cast<float*>(smh);   // TM*LDE*4 <= smem budget
#pragma unroll
    for (int i = 0; i < 2; i++)
#pragma unroll
        for (int j = 0; j < NB; j++)
            wmma::store_matrix_sync(stf + (wr * 32 + i * 16) * LDE + wc * CW + j * 16,
                                    acc[i][j], LDE, wmma::mem_row_major);
    __syncthreads();
    constexpr int WITER = TM * 32 / 256;          // TM rows x 32 float4 cols
#pragma unroll
    for (int i = 0; i < WITER; i++) {
        int f = i * 256 + tid;
        int r = f >> 5, c = (f & 31) << 2;
        float4 v  = *reinterpret_cast<float4*>(stf + r * LDE + c);
        float4 bv = *reinterpret_cast<const float4*>(bias + n0 + c);
        v.x += bv.x; v.y += bv.y; v.z += bv.z; v.w += bv.w;
        if (!OUT_HALF) {
            *reinterpret_cast<float4*>((float*)Yv + (size_t)(m0 + r) * DM + n0 + c) = v;
        } else {
            __half2 h0 = __floats2half2_rn(v.x * scale, v.y * scale);
            __half2 h1 = __floats2half2_rn(v.z * scale, v.w * scale);
            uint2 u;
            u.x = *reinterpret_cast<uint32_t*>(&h0);
            u.y = *reinterpret_cast<uint32_t*>(&h1);
            int h    = (n0 + c) >> 6;
            int bidx = (m0 + r) / seq;
            int l    = (m0 + r) % seq;
            *reinterpret_cast<uint2*>((__half*)Yv +
                (((size_t)(bidx * NH + h) * seq + l) << 6) + (c & 63)) = u;
        }
    }
}

__global__ __launch_bounds__(256, 2) void gemm_qkv(
    const __half* __restrict__ xq, const __half* __restrict__ xkv,
    const __half* __restrict__ wq, const __half* __restrict__ wk,
    const __half* __restrict__ wv,
    const float* __restrict__ bq, const float* __restrict__ bk,
    const float* __restrict__ bv,
    __half* __restrict__ Qh, __half* __restrict__ Kh, __half* __restrict__ Vh)
{
    using namespace cfg;
    extern __shared__ __half smh[];
    const int ty = blockIdx.y;
    const int n0 = blockIdx.x * 128;

    const __half *X, *W; const float* bias; __half* Y;
    int seq, m0; float scale;
    if (ty < 16)      { X = xq;  W = wq; bias = bq; Y = Qh; seq = LQ;  scale = 0.125f; m0 = ty * 128; }
    else if (ty < 80) { X = xkv; W = wk; bias = bk; Y = Kh; seq = LKV; scale = 1.0f;   m0 = (ty - 16) * 128; }
    else              { X = xkv; W = wv; bias = bv; Y = Vh; seq = LKV; scale = 1.0f;   m0 = (ty - 80) * 128; }

    gemm_body<true, 128>(X, W, bias, Y, m0, n0, seq, scale, smh);
}

__global__ __launch_bounds__(256, 2) void gemm_o(
    const __half* __restrict__ X, const __half* __restrict__ W,
    const float* __restrict__ bias, float* __restrict__ Y)
{
    using namespace cfg;
    extern __shared__ __half smh[];
    gemm_body<false, 64>(X, W, bias, Y, blockIdx.y * 64, blockIdx.x * 128,
                         0, 1.0f, smh);
}

// ---------------------------------------------------------------------------
// Attention (byte-reverted to R11): register-resident softmax via mma.m16n8k16.
// Block = (b,h) x 128-q tile, 8 warps, warp = 16 q-rows. KV chunk 64,
// double-buffered cp.async. Q fragments loaded by ldmatrix ONCE. S lives in
// acc registers; row sums in 2 regs/thread; one normalization at the end.
// ---------------------------------------------------------------------------
__global__ __launch_bounds__(256, 2) void attn_h(
    const __half* __restrict__ Qg, const __half* __restrict__ Kg,
    const __half* __restrict__ Vg, __half* __restrict__ ctx)
{
    using namespace cfg;
    extern __shared__ char smb[];
    __half* sQ    = (__half*)(smb);                                   // 128*72*2
    __half* sK[2] = { (__half*)(smb + 18432), (__half*)(smb + 27648) }; // 64*72*2
    __half* sV[2] = { (__half*)(smb + 36864), (__half*)(smb + 46080) };
    const uint32_t sQa = smem_u32(sQ);
    const uint32_t sKa[2] = { smem_u32(sK[0]), smem_u32(sK[1]) };
    const uint32_t sVa[2] = { smem_u32(sV[0]), smem_u32(sV[1]) };

    const int tid  = threadIdx.x;
    const int warp = tid >> 5;
    const int lane = tid & 31;
    const int bh   = blockIdx.y;
    const int q0   = blockIdx.x * 128;

    const __half* Q = Qg + (size_t)bh * LQ  * HD;
    const __half* K = Kg + (size_t)bh * LKV * HD;
    const __half* V = Vg + (size_t)bh * LKV * HD;

    // ldmatrix lane geometry
    const int grp = lane >> 3, li = lane & 7;
    const int krow = ((grp >> 1) << 3) + li, kcol = (grp & 1) << 3;  // K (b-frags)
    const int vrow = ((grp & 1) << 3) + li, vcol = (grp >> 1) << 3;  // V (.trans), Q (a-frags)

    auto stage_kv = [&](int s, int kc) {
#pragma unroll
        for (int i = 0; i < 2; i++) {
            int f = i * 256 + tid;
            int r = f >> 3, c8 = (f & 7) * 8;
            CP_ASYNC16(sKa[s] + (uint32_t)(r * LDH + c8) * 2,
                       K + (size_t)(kc * 64 + r) * HD + c8);
            CP_ASYNC16(sVa[s] + (uint32_t)(r * LDH + c8) * 2,
                       V + (size_t)(kc * 64 + r) * HD + c8);
        }
        CP_ASYNC_COMMIT();
    };

    // Prologue: Q tile + KV chunk 0 (single commit group).
#pragma unroll
    for (int i = 0; i < 4; i++) {
        int f = i * 256 + tid;
        int r = f >> 3, c8 = (f & 7) * 8;
        CP_ASYNC16(sQa + (uint32_t)(r * LDH + c8) * 2,
                   Q + (size_t)(q0 + r) * HD + c8);
    }
    stage_kv(0, 0);

    uint32_t qa[4][4];
    float oacc[8][4];
#pragma unroll
    for (int j = 0; j < 8; j++)
#pragma unroll
        for (int t = 0; t < 4; t++) oacc[j][t] = 0.0f;
    float rs0 = 0.0f, rs1 = 0.0f;

    for (int kc = 0; kc < LKV / 64; kc++) {
        const int s = kc & 1;
        if (kc + 1 < LKV / 64) { stage_kv(1 - s, kc + 1); CP_ASYNC_WAIT1(); }
        else                   { CP_ASYNC_WAIT0(); }
        __syncthreads();

        if (kc == 0) {   // load Q a-frags once (reused for all chunks)
#pragma unroll
            for (int ks = 0; ks < 4; ks++)
                ldsm_x4(qa[ks][0], qa[ks][1], qa[ks][2], qa[ks][3],
                        sQa + (uint32_t)((warp * 16 + vrow) * LDH + ks * 16 + vcol) * 2);
        }

        // ---- S = Q @ K^T : 8 n8-tiles (kv), fp32 acc in registers ----
        float sc[8][4];
#pragma unroll
        for (int j = 0; j < 8; j++)
#pragma unroll
            for (int t = 0; t < 4; t++) sc[j][t] = 0.0f;
#pragma unroll
        for (int ks = 0; ks < 4; ks++) {
#pragma unroll
            for (int jt = 0; jt < 4; jt++) {
                uint32_t b0, b1, b2, b3;
                ldsm_x4(b0, b1, b2, b3,
                        sKa[s] + (uint32_t)((jt * 16 + krow) * LDH + ks * 16 + kcol) * 2);
                mma16816(sc[2 * jt],     qa[ks], b0, b1);
                mma16816(sc[2 * jt + 1], qa[ks], b2, b3);
            }
        }

        // ---- P = half(exp(S)) packed directly into PV A-frags ----
        uint32_t pa[4][4];
#pragma unroll
        for (int J = 0; J < 4; J++) {
            float* e0 = sc[2 * J];
            float* e1 = sc[2 * J + 1];
            __half2 h00 = __floats2half2_rn(__expf(e0[0]), __expf(e0[1]));  // row r
            __half2 h01 = __floats2half2_rn(__expf(e0[2]), __expf(e0[3]));  // row r+8
            __half2 h10 = __floats2half2_rn(__expf(e1[0]), __expf(e1[1]));
            __half2 h11 = __floats2half2_rn(__expf(e1[2]), __expf(e1[3]));
            pa[J][0] = *reinterpret_cast<uint32_t*>(&h00);
            pa[J][1] = *reinterpret_cast<uint32_t*>(&h01);
            pa[J][2] = *reinterpret_cast<uint32_t*>(&h10);
            pa[J][3] = *reinterpret_cast<uint32_t*>(&h11);
            float2 f00 = __half22float2(h00), f01 = __half22float2(h01);
            float2 f10 = __half22float2(h10), f11 = __half22float2(h11);
            rs0 += f00.x + f00.y + f10.x + f10.y;
            rs1 += f01.x + f01.y + f11.x + f11.y;
        }

        // ---- O += P @ V : 8 n8-tiles (head dim) ----
#pragma unroll
        for (int J = 0; J < 4; J++) {
#pragma unroll
            for (int dt = 0; dt < 4; dt++) {
                uint32_t b0, b1, b2, b3;
                ldsm_x4_t(b0, b1, b2, b3,
                          sVa[s] + (uint32_t)((J * 16 + vrow) * LDH + dt * 16 + vcol) * 2);
                mma16816(oacc[2 * dt],     pa[J], b0, b1);
                mma16816(oacc[2 * dt + 1], pa[J], b2, b3);
            }
        }
        __syncthreads();   // all warps done with buffer s before restaging
    }

    // ---- finalize row sums (quad reduce) and write normalized O ----
    rs0 += __shfl_xor_sync(0xffffffffu, rs0, 1);
    rs0 += __shfl_xor_sync(0xffffffffu, rs0, 2);
    rs1 += __shfl_xor_sync(0xffffffffu, rs1, 1);
    rs1 += __shfl_xor_sync(0xffffffffu, rs1, 2);
    const float i0 = 1.0f / rs0, i1 = 1.0f / rs1;

    const int b  = bh / NH, hh = bh % NH;
    const int r0 = q0 + warp * 16 + (lane >> 2);
    const int cb = (lane & 3) * 2;
#pragma unroll
    for (int j = 0; j < 8; j++) {
        __half2 h0 = __floats2half2_rn(oacc[j][0] * i0, oacc[j][1] * i0);
        __half2 h1 = __floats2half2_rn(oacc[j][2] * i1, oacc[j][3] * i1);
        *reinterpret_cast<__half2*>(ctx +
            (((size_t)(b * LQ + r0) * NH + hh) << 6) + 8 * j + cb) = h0;
        *reinterpret_cast<__half2*>(ctx +
            (((size_t)(b * LQ + r0 + 8) * NH + hh) << 6) + 8 * j + cb) = h1;
    }
}

// ---------------------------------------------------------------------------
extern "C" void kernel_launch(void* const* d_in, const int* in_sizes, int n_in,
                              void* d_out, int out_size)
{
    using namespace cfg;
    (void)in_sizes; (void)n_in; (void)out_size;

    const float* q  = (const float*)d_in[0];
    const float* kv = (const float*)d_in[1];
    const float* Wq = (const float*)d_in[2];
    const float* bq = (const float*)d_in[3];
    const float* Wk = (const float*)d_in[4];
    const float* bk = (const float*)d_in[5];
    const float* Wv = (const float*)d_in[6];
    const float* bv = (const float*)d_in[7];
    const float* Wo = (const float*)d_in[8];
    const float* bo = (const float*)d_in[9];
    float* out = (float*)d_out;

    void *p_xq, *p_xkv, *p_wq, *p_wk, *p_wv, *p_wo, *p_Q, *p_K, *p_V, *p_ctx;
    cudaGetSymbolAddress(&p_xq,  g_xq);
    cudaGetSymbolAddress(&p_xkv, g_xkv);
    cudaGetSymbolAddress(&p_wq,  g_wq);
    cudaGetSymbolAddress(&p_wk,  g_wk);
    cudaGetSymbolAddress(&p_wv,  g_wv);
    cudaGetSymbolAddress(&p_wo,  g_wo);
    cudaGetSymbolAddress(&p_Q,   g_Qh);
    cudaGetSymbolAddress(&p_K,   g_Kh);
    cudaGetSymbolAddress(&p_V,   g_Vh);
    cudaGetSymbolAddress(&p_ctx, g_ctx);
    __half* xq  = (__half*)p_xq;
    __half* xkv = (__half*)p_xkv;
    __half* ctx = (__half*)p_ctx;

    const int GEMM_SMEM   = 4 * 128 * LDH * 2;          // 73728 B (TM=128)
    const int GEMM_SMEM_O = 2 * (64 + 128) * LDH * 2;   // 55296 B (TM=64)
    const int ATT_SMEM    = 55296;                      // sQ + 2x(64-row K,V)
    cudaFuncSetAttribute(gemm_qkv,
                         cudaFuncAttributeMaxDynamicSharedMemorySize, GEMM_SMEM);
    cudaFuncSetAttribute(gemm_o,
                         cudaFuncAttributeMaxDynamicSharedMemorySize, GEMM_SMEM_O);
    cudaFuncSetAttribute(attn_h,
                         cudaFuncAttributeMaxDynamicSharedMemorySize, ATT_SMEM);

    F2HArgs fa;
    fa.src[0] = q;   fa.dst[0] = xq;             fa.n[0] = B * LQ  * DM;
    fa.src[1] = kv;  fa.dst[1] = xkv;            fa.n[1] = B * LKV * DM;
    fa.src[2] = Wq;  fa.dst[2] = (__half*)p_wq;  fa.n[2] = DM * DM;
    fa.src[3] = Wk;  fa.dst[3] = (__half*)p_wk;  fa.n[3] = DM * DM;
    fa.src[4] = Wv;  fa.dst[4] = (__half*)p_wv;  fa.n[4] = DM * DM;
    fa.src[5] = Wo;  fa.dst[5] = (__half*)p_wo;  fa.n[5] = DM * DM;
    f2h_all<<<1024, 256>>>(fa);

    const dim3 blk(256);

    gemm_qkv<<<dim3(DM / 128, 144), blk, GEMM_SMEM>>>(
        xq, xkv, (__half*)p_wq, (__half*)p_wk, (__half*)p_wv,
        bq, bk, bv, (__half*)p_Q, (__half*)p_K, (__half*)p_V);

    attn_h<<<dim3(LQ / 128, B * NH), blk, ATT_SMEM>>>(
        (__half*)p_Q, (__half*)p_K, (__half*)p_V, ctx);

    // O-proj: 64-row m-tiles -> 256 blocks (was 128; fills the occ-2 wave).
    gemm_o<<<dim3(DM / 128, (B * LQ) / 64), blk, GEMM_SMEM_O>>>(
        ctx, (__half*)p_wo, bo, out);
}

// round 14
// speedup vs baseline: 1.0711x; 1.0010x over previous
#include <cuda_runtime.h>
#include <cuda_fp16.h>
#include <mma.h>
#include <cstdint>

using namespace nvcuda;

namespace cfg {
constexpr int DM  = 1024;
constexpr int NH  = 16;
constexpr int HD  = 64;
constexpr int B   = 4;
constexpr int LQ  = 512;
constexpr int LKV = 2048;
constexpr int LDH = 72;    // half leading dim (64+8): 144B rows, LDSM conflict-free
constexpr int LDE = 132;   // gemm epilogue fp32 staging leading dim
}

// -------- half scratch (inputs pre-converted once) -------------------------
__device__ __half g_xq [(size_t)cfg::B * cfg::LQ  * cfg::DM];
__device__ __half g_xkv[(size_t)cfg::B * cfg::LKV * cfg::DM];
__device__ __half g_wq [(size_t)cfg::DM * cfg::DM];
__device__ __half g_wk [(size_t)cfg::DM * cfg::DM];
__device__ __half g_wv [(size_t)cfg::DM * cfg::DM];
__device__ __half g_wo [(size_t)cfg::DM * cfg::DM];
__device__ __half g_Qh [(size_t)cfg::B * cfg::NH * cfg::LQ  * cfg::HD];
__device__ __half g_Kh [(size_t)cfg::B * cfg::NH * cfg::LKV * cfg::HD];
__device__ __half g_Vh [(size_t)cfg::B * cfg::NH * cfg::LKV * cfg::HD];
__device__ __half g_ctx[(size_t)cfg::B * cfg::LQ * cfg::DM];

__device__ __forceinline__ uint32_t smem_u32(const void* p) {
    uint32_t a;
    asm("{ .reg .u64 t; cvta.to.shared.u64 t, %1; cvt.u32.u64 %0, t; }"
        : "=r"(a) : "l"(p));
    return a;
}
#define CP_ASYNC16(dst_u32, src_ptr) \
    asm volatile("cp.async.cg.shared.global [%0], [%1], 16;" \
                 :: "r"(dst_u32), "l"(src_ptr) : "memory")
#define CP_ASYNC_COMMIT() asm volatile("cp.async.commit_group;" ::: "memory")
#define CP_ASYNC_WAIT0()  asm volatile("cp.async.wait_group 0;" ::: "memory")
#define CP_ASYNC_WAIT1()  asm volatile("cp.async.wait_group 1;" ::: "memory")

__device__ __forceinline__ void ldsm_x4(uint32_t& r0, uint32_t& r1,
                                        uint32_t& r2, uint32_t& r3, uint32_t addr) {
    asm volatile("ldmatrix.sync.aligned.m8n8.x4.shared.b16 {%0,%1,%2,%3}, [%4];"
                 : "=r"(r0), "=r"(r1), "=r"(r2), "=r"(r3) : "r"(addr));
}
__device__ __forceinline__ void ldsm_x4_t(uint32_t& r0, uint32_t& r1,
                                          uint32_t& r2, uint32_t& r3, uint32_t addr) {
    asm volatile("ldmatrix.sync.aligned.m8n8.x4.trans.shared.b16 {%0,%1,%2,%3}, [%4];"
                 : "=r"(r0), "=r"(r1), "=r"(r2), "=r"(r3) : "r"(addr));
}
__device__ __forceinline__ void mma16816(float* d, const uint32_t* a,
                                         uint32_t b0, uint32_t b1) {
    asm volatile(
        "mma.sync.aligned.m16n8k16.row.col.f32.f16.f16.f32 "
        "{%0,%1,%2,%3}, {%4,%5,%6,%7}, {%8,%9}, {%0,%1,%2,%3};"
        : "+f"(d[0]), "+f"(d[1]), "+f"(d[2]), "+f"(d[3])
        : "r"(a[0]), "r"(a[1]), "r"(a[2]), "r"(a[3]), "r"(b0), "r"(b1));
}

// ---------------------------------------------------------------------------
// fp32 -> fp16 bulk convert, all six tensors in one launch.
// ---------------------------------------------------------------------------
struct F2HArgs {
    const float* src[6];
    __half*      dst[6];
    int          n[6];
};
__global__ void f2h_all(F2HArgs p)
{
#pragma unroll
    for (int seg = 0; seg < 6; seg++) {
        const float* a = p.src[seg];
        __half*      b = p.dst[seg];
        const int    n = p.n[seg];
        int i = (blockIdx.x * blockDim.x + threadIdx.x) * 4;
        int stride = gridDim.x * blockDim.x * 4;
        for (; i < n; i += stride) {
            float4 v = *reinterpret_cast<const float4*>(a + i);
            __half2 h0 = __floats2half2_rn(v.x, v.y);
            __half2 h1 = __floats2half2_rn(v.z, v.w);
            uint2 u;
            u.x = *reinterpret_cast<uint32_t*>(&h0);
            u.y = *reinterpret_cast<uint32_t*>(&h1);
            *reinterpret_cast<uint2*>(b + i) = u;
        }
    }
}

// ---------------------------------------------------------------------------
// QKV GEMM: 256x128 CTA tile, 8 warps, WARP TILE 64x64 (4x2 strips):
// per k-16 step a warp does 8 fragment loads -> 16 MMAs (2x the old 32x64
// MMA:LDS ratio) and halves W traffic per output. K-chunk 64, 2-stage cp.async.
// Epilogue stages 128 rows at a time (two passes).
// ---------------------------------------------------------------------------
__global__ __launch_bounds__(256, 1) void gemm_qkv(
    const __half* __restrict__ xq, const __half* __restrict__ xkv,
    const __half* __restrict__ wq, const __half* __restrict__ wk,
    const __half* __restrict__ wv,
    const float* __restrict__ bq, const float* __restrict__ bk,
    const float* __restrict__ bv,
    __half* __restrict__ Qh, __half* __restrict__ Kh, __half* __restrict__ Vh)
{
    using namespace cfg;
    constexpr int TM = 256, KC = 64, NCH = DM / KC;   // 16 chunks
    constexpr int BUFX = TM  * LDH;                   // 18432 halves
    constexpr int BUFW = 128 * LDH;                   //  9216 halves
    extern __shared__ __half smh[];
    __half* bx[2] = { smh,               smh + BUFX + BUFW };
    __half* bw[2] = { smh + BUFX,        smh + 2 * BUFX + BUFW };
    const uint32_t bxa[2] = { smem_u32(bx[0]), smem_u32(bx[1]) };
    const uint32_t bwa[2] = { smem_u32(bw[0]), smem_u32(bw[1]) };

    const int tid  = threadIdx.x;
    const int warp = tid >> 5;
    const int wr   = warp >> 1;          // 0..3 : 64-row strip
    const int wc   = warp & 1;           // 0..1 : 64-col strip
    const int ty   = blockIdx.y;
    const int n0   = blockIdx.x * 128;

    const __half *X, *W; const float* bias; __half* Y;
    int seq, m0; float scale;
    if (ty < 8)       { X = xq;  W = wq; bias = bq; Y = Qh; seq = LQ;  scale = 0.125f; m0 = ty * TM; }
    else if (ty < 40) { X = xkv; W = wk; bias = bk; Y = Kh; seq = LKV; scale = 1.0f;   m0 = (ty - 8)  * TM; }
    else              { X = xkv; W = wv; bias = bv; Y = Vh; seq = LKV; scale = 1.0f;   m0 = (ty - 40) * TM; }

    wmma::fragment<wmma::accumulator, 16, 16, 16, float> acc[4][4];
#pragma unroll
    for (int i = 0; i < 4; i++)
#pragma unroll
        for (int j = 0; j < 4; j++) wmma::fill_fragment(acc[i][j], 0.0f);

    // Stage one 64-deep K-chunk: X (256 rows) + W (128 rows) = 384 rows.
    auto stage = [&](int s, int k0) {
#pragma unroll
        for (int i = 0; i < 12; i++) {
            int f = i * 256 + tid;              // 0..3071
            int r = f >> 3, c8 = (f & 7) * 8;
            if (r < TM) {
                CP_ASYNC16(bxa[s] + (uint32_t)(r * LDH + c8) * 2,
                           X + (size_t)(m0 + r) * DM + k0 + c8);
            } else {
                int rw = r - TM;
                CP_ASYNC16(bwa[s] + (uint32_t)(rw * LDH + c8) * 2,
                           W + (size_t)(n0 + rw) * DM + k0 + c8);
            }
        }
        CP_ASYNC_COMMIT();
    };

    stage(0, 0);
    for (int kc = 0; kc < NCH; kc++) {
        const int s = kc & 1;
        if (kc + 1 < NCH) { stage(1 - s, (kc + 1) * KC); CP_ASYNC_WAIT1(); }
        else              { CP_ASYNC_WAIT0(); }
        __syncthreads();
#pragma unroll
        for (int kk = 0; kk < KC; kk += 16) {
            wmma::fragment<wmma::matrix_a, 16, 16, 16, __half, wmma::row_major> a[4];
#pragma unroll
            for (int i = 0; i < 4; i++)
                wmma::load_matrix_sync(a[i], bx[s] + (wr * 64 + i * 16) * LDH + kk, LDH);
#pragma unroll
            for (int j = 0; j < 4; j++) {
                wmma::fragment<wmma::matrix_b, 16, 16, 16, __half, wmma::col_major> bf;
                wmma::load_matrix_sync(bf, bw[s] + (wc * 64 + j * 16) * LDH + kk, LDH);
#pragma unroll
                for (int i = 0; i < 4; i++)
                    wmma::mma_sync(acc[i][j], a[i], bf, acc[i][j]);
            }
        }
        __syncthreads();
    }

    // Epilogue: two 128-row passes (256 x LDE fp32 won't fit in smem).
    float* stf = reinterpret_cast<float*>(smh);   // 128*LDE*4 = 67584 <= 110592
#pragma unroll
    for (int h = 0; h < 2; h++) {
        if ((wr >> 1) == h) {     // warps owning rows [h*128, h*128+128)
#pragma unroll
            for (int i = 0; i < 4; i++)
#pragma unroll
                for (int j = 0; j < 4; j++)
                    wmma::store_matrix_sync(
                        stf + ((wr & 1) * 64 + i * 16) * LDE + wc * 64 + j * 16,
                        acc[i][j], LDE, wmma::mem_row_major);
        }
        __syncthreads();
#pragma unroll
        for (int i = 0; i < 16; i++) {
            int f = i * 256 + tid;
            int r = f >> 5, c = (f & 31) << 2;    // 128 rows x 32 float4
            float4 v  = *reinterpret_cast<float4*>(stf + r * LDE + c);
            float4 bv = *reinterpret_cast<const float4*>(bias + n0 + c);
            __half2 h0 = __floats2half2_rn((v.x + bv.x) * scale, (v.y + bv.y) * scale);
            __half2 h1 = __floats2half2_rn((v.z + bv.z) * scale, (v.w + bv.w) * scale);
            uint2 u;
            u.x = *reinterpret_cast<uint32_t*>(&h0);
            u.y = *reinterpret_cast<uint32_t*>(&h1);
            int gr   = m0 + h * 128 + r;
            int hd   = (n0 + c) >> 6;
            int bidx = gr / seq;
            int l    = gr % seq;
            *reinterpret_cast<uint2*>(Y +
                (((size_t)(bidx * NH + hd) * seq + l) << 6) + (c & 63)) = u;
        }
        __syncthreads();
    }
}

// ---------------------------------------------------------------------------
// O-proj GEMM (exact R11 body): 128x128 tile, 8 warps (32x64), K-chunk 64,
// 2-stage cp.async, fp32 output.
// ---------------------------------------------------------------------------
__global__ __launch_bounds__(256, 2) void gemm_o(
    const __half* __restrict__ X, const __half* __restrict__ W,
    const float* __restrict__ bias, float* __restrict__ Y)
{
    using namespace cfg;
    constexpr int KC = 64, NCH = DM / KC;
    extern __shared__ __half smh[];
    __half* bx[2] = { smh,                smh + 2 * 128 * LDH };
    __half* bw[2] = { smh + 128 * LDH,    smh + 3 * 128 * LDH };
    const uint32_t bxa[2] = { smem_u32(bx[0]), smem_u32(bx[1]) };
    const uint32_t bwa[2] = { smem_u32(bw[0]), smem_u32(bw[1]) };

    const int tid  = threadIdx.x;
    const int warp = tid >> 5;
    const int wr   = warp >> 1;
    const int wc   = warp & 1;
    const int m0   = blockIdx.y * 128;
    const int n0   = blockIdx.x * 128;

    wmma::fragment<wmma::accumulator, 16, 16, 16, float> acc[2][4];
#pragma unroll
    for (int i = 0; i < 2; i++)
#pragma unroll
        for (int j = 0; j < 4; j++) wmma::fill_fragment(acc[i][j], 0.0f);

    auto stage = [&](int s, int k0) {
#pragma unroll
        for (int i = 0; i < 4; i++) {
            int f = i * 256 + tid;
            int r = f >> 3, c8 = (f & 7) * 8;
            CP_ASYNC16(bxa[s] + (uint32_t)(r * LDH + c8) * 2,
                       X + (size_t)(m0 + r) * DM + k0 + c8);
            CP_ASYNC16(bwa[s] + (uint32_t)(r * LDH + c8) * 2,
                       W + (size_t)(n0 + r) * DM + k0 + c8);
        }
        CP_ASYNC_COMMIT();
    };

    stage(0, 0);
    for (int kc = 0; kc < NCH; kc++) {
        const int s = kc & 1;
        if (kc + 1 < NCH) { stage(1 - s, (kc + 1) * KC); CP_ASYNC_WAIT1(); }
        else              { CP_ASYNC_WAIT0(); }
        __syncthreads();
#pragma unroll
        for (int kk = 0; kk < KC; kk += 16) {
            wmma::fragment<wmma::matrix_a, 16, 16, 16, __half, wmma::row_major> a[2];
#pragma unroll
            for (int i = 0; i < 2; i++)
                wmma::load_matrix_sync(a[i], bx[s] + (wr * 32 + i * 16) * LDH + kk, LDH);
#pragma unroll
            for (int j = 0; j < 4; j++) {
                wmma::fragment<wmma::matrix_b, 16, 16, 16, __half, wmma::col_major> bf;
                wmma::load_matrix_sync(bf, bw[s] + (wc * 64 + j * 16) * LDH + kk, LDH);
#pragma unroll
                for (int i = 0; i < 2; i++)
                    wmma::mma_sync(acc[i][j], a[i], bf, acc[i][j]);
            }
        }
        __syncthreads();
    }

    float* stf = reinterpret_cast<float*>(smh);
#pragma unroll
    for (int i = 0; i < 2; i++)
#pragma unroll
        for (int j = 0; j < 4; j++)
            wmma::store_matrix_sync(stf + (wr * 32 + i * 16) * LDE + wc * 64 + j * 16,
                                    acc[i][j], LDE, wmma::mem_row_major);
    __syncthreads();
#pragma unroll
    for (int i = 0; i < 16; i++) {
        int f = i * 256 + tid;
        int r = f >> 5, c = (f & 31) << 2;
        float4 v  = *reinterpret_cast<float4*>(stf + r * LDE + c);
        float4 bv = *reinterpret_cast<const float4*>(bias + n0 + c);
        v.x += bv.x; v.y += bv.y; v.z += bv.z; v.w += bv.w;
        *reinterpret_cast<float4*>(Y + (size_t)(m0 + r) * DM + n0 + c) = v;
    }
}

// ---------------------------------------------------------------------------
// Attention (exact R11): register-resident softmax via mma.m16n8k16.
// ---------------------------------------------------------------------------
__global__ __launch_bounds__(256, 2) void attn_h(
    const __half* __restrict__ Qg, const __half* __restrict__ Kg,
    const __half* __restrict__ Vg, __half* __restrict__ ctx)
{
    using namespace cfg;
    extern __shared__ char smb[];
    __half* sQ    = (__half*)(smb);                                   // 128*72*2
    __half* sK[2] = { (__half*)(smb + 18432), (__half*)(smb + 27648) }; // 64*72*2
    __half* sV[2] = { (__half*)(smb + 36864), (__half*)(smb + 46080) };
    const uint32_t sQa = smem_u32(sQ);
    const uint32_t sKa[2] = { smem_u32(sK[0]), smem_u32(sK[1]) };
    const uint32_t sVa[2] = { smem_u32(sV[0]), smem_u32(sV[1]) };

    const int tid  = threadIdx.x;
    const int warp = tid >> 5;
    const int lane = tid & 31;
    const int bh   = blockIdx.y;
    const int q0   = blockIdx.x * 128;

    const __half* Q = Qg + (size_t)bh * LQ  * HD;
    const __half* K = Kg + (size_t)bh * LKV * HD;
    const __half* V = Vg + (size_t)bh * LKV * HD;

    const int grp = lane >> 3, li = lane & 7;
    const int krow = ((grp >> 1) << 3) + li, kcol = (grp & 1) << 3;
    const int vrow = ((grp & 1) << 3) + li, vcol = (grp >> 1) << 3;

    auto stage_kv = [&](int s, int kc) {
#pragma unroll
        for (int i = 0; i < 2; i++) {
            int f = i * 256 + tid;
            int r = f >> 3, c8 = (f & 7) * 8;
            CP_ASYNC16(sKa[s] + (uint32_t)(r * LDH + c8) * 2,
                       K + (size_t)(kc * 64 + r) * HD + c8);
            CP_ASYNC16(sVa[s] + (uint32_t)(r * LDH + c8) * 2,
                       V + (size_t)(kc * 64 + r) * HD + c8);
        }
        CP_ASYNC_COMMIT();
    };

#pragma unroll
    for (int i = 0; i < 4; i++) {
        int f = i * 256 + tid;
        int r = f >> 3, c8 = (f & 7) * 8;
        CP_ASYNC16(sQa + (uint32_t)(r * LDH + c8) * 2,
                   Q + (size_t)(q0 + r) * HD + c8);
    }
    stage_kv(0, 0);

    uint32_t qa[4][4];
    float oacc[8][4];
#pragma unroll
    for (int j = 0; j < 8; j++)
#pragma unroll
        for (int t = 0; t < 4; t++) oacc[j][t] = 0.0f;
    float rs0 = 0.0f, rs1 = 0.0f;

    for (int kc = 0; kc < LKV / 64; kc++) {
        const int s = kc & 1;
        if (kc + 1 < LKV / 64) { stage_kv(1 - s, kc + 1); CP_ASYNC_WAIT1(); }
        else                   { CP_ASYNC_WAIT0(); }
        __syncthreads();

        if (kc == 0) {
#pragma unroll
            for (int ks = 0; ks < 4; ks++)
                ldsm_x4(qa[ks][0], qa[ks][1], qa[ks][2], qa[ks][3],
                        sQa + (uint32_t)((warp * 16 + vrow) * LDH + ks * 16 + vcol) * 2);
        }

        float sc[8][4];
#pragma unroll
        for (int j = 0; j < 8; j++)
#pragma unroll
            for (int t = 0; t < 4; t++) sc[j][t] = 0.0f;
#pragma unroll
        for (int ks = 0; ks < 4; ks++) {
#pragma unroll
            for (int jt = 0; jt < 4; jt++) {
                uint32_t b0, b1, b2, b3;
                ldsm_x4(b0, b1, b2, b3,
                        sKa[s] + (uint32_t)((jt * 16 + krow) * LDH + ks * 16 + kcol) * 2);
                mma16816(sc[2 * jt],     qa[ks], b0, b1);
                mma16816(sc[2 * jt + 1], qa[ks], b2, b3);
            }
        }

        uint32_t pa[4][4];
#pragma unroll
        for (int J = 0; J < 4; J++) {
            float* e0 = sc[2 * J];
            float* e1 = sc[2 * J + 1];
            __half2 h00 = __floats2half2_rn(__expf(e0[0]), __expf(e0[1]));
            __half2 h01 = __floats2half2_rn(__expf(e0[2]), __expf(e0[3]));
            __half2 h10 = __floats2half2_rn(__expf(e1[0]), __expf(e1[1]));
            __half2 h11 = __floats2half2_rn(__expf(e1[2]), __expf(e1[3]));
            pa[J][0] = *reinterpret_cast<uint32_t*>(&h00);
            pa[J][1] = *reinterpret_cast<uint32_t*>(&h01);
            pa[J][2] = *reinterpret_cast<uint32_t*>(&h10);
            pa[J][3] = *reinterpret_cast<uint32_t*>(&h11);
            float2 f00 = __half22float2(h00), f01 = __half22float2(h01);
            float2 f10 = __half22float2(h10), f11 = __half22float2(h11);
            rs0 += f00.x + f00.y + f10.x + f10.y;
            rs1 += f01.x + f01.y + f11.x + f11.y;
        }

#pragma unroll
        for (int J = 0; J < 4; J++) {
#pragma unroll
            for (int dt = 0; dt < 4; dt++) {
                uint32_t b0, b1, b2, b3;
                ldsm_x4_t(b0, b1, b2, b3,
                          sVa[s] + (uint32_t)((J * 16 + vrow) * LDH + dt * 16 + vcol) * 2);
                mma16816(oacc[2 * dt],     pa[J], b0, b1);
                mma16816(oacc[2 * dt + 1], pa[J], b2, b3);
            }
        }
        __syncthreads();
    }

    rs0 += __shfl_xor_sync(0xffffffffu, rs0, 1);
    rs0 += __shfl_xor_sync(0xffffffffu, rs0, 2);
    rs1 += __shfl_xor_sync(0xffffffffu, rs1, 1);
    rs1 += __shfl_xor_sync(0xffffffffu, rs1, 2);
    const float i0 = 1.0f / rs0, i1 = 1.0f / rs1;

    const int b  = bh / NH, hh = bh % NH;
    const int r0 = q0 + warp * 16 + (lane >> 2);
    const int cb = (lane & 3) * 2;
#pragma unroll
    for (int j = 0; j < 8; j++) {
        __half2 h0 = __floats2half2_rn(oacc[j][0] * i0, oacc[j][1] * i0);
        __half2 h1 = __floats2half2_rn(oacc[j][2] * i1, oacc[j][3] * i1);
        *reinterpret_cast<__half2*>(ctx +
            (((size_t)(b * LQ + r0) * NH + hh) << 6) + 8 * j + cb) = h0;
        *reinterpret_cast<__half2*>(ctx +
            (((size_t)(b * LQ + r0 + 8) * NH + hh) << 6) + 8 * j + cb) = h1;
    }
}

// ---------------------------------------------------------------------------
extern "C" void kernel_launch(void* const* d_in, const int* in_sizes, int n_in,
                              void* d_out, int out_size)
{
    using namespace cfg;
    (void)in_sizes; (void)n_in; (void)out_size;

    const float* q  = (const float*)d_in[0];
    const float* kv = (const float*)d_in[1];
    const float* Wq = (const float*)d_in[2];
    const float* bq = (const float*)d_in[3];
    const float* Wk = (const float*)d_in[4];
    const float* bk = (const float*)d_in[5];
    const float* Wv = (const float*)d_in[6];
    const float* bv = (const float*)d_in[7];
    const float* Wo = (const float*)d_in[8];
    const float* bo = (const float*)d_in[9];
    float* out = (float*)d_out;

    void *p_xq, *p_xkv, *p_wq, *p_wk, *p_wv, *p_wo, *p_Q, *p_K, *p_V, *p_ctx;
    cudaGetSymbolAddress(&p_xq,  g_xq);
    cudaGetSymbolAddress(&p_xkv, g_xkv);
    cudaGetSymbolAddress(&p_wq,  g_wq);
    cudaGetSymbolAddress(&p_wk,  g_wk);
    cudaGetSymbolAddress(&p_wv,  g_wv);
    cudaGetSymbolAddress(&p_wo,  g_wo);
    cudaGetSymbolAddress(&p_Q,   g_Qh);
    cudaGetSymbolAddress(&p_K,   g_Kh);
    cudaGetSymbolAddress(&p_V,   g_Vh);
    cudaGetSymbolAddress(&p_ctx, g_ctx);
    __half* xq  = (__half*)p_xq;
    __half* xkv = (__half*)p_xkv;
    __half* ctx = (__half*)p_ctx;

    const int QKV_SMEM  = 2 * (256 + 128) * cfg::LDH * 2;   // 110592 B
    const int O_SMEM    = 4 * 128 * cfg::LDH * 2;           // 73728 B
    const int ATT_SMEM  = 55296;
    cudaFuncSetAttribute(gemm_qkv,
                         cudaFuncAttributeMaxDynamicSharedMemorySize, QKV_SMEM);
    cudaFuncSetAttribute(gemm_o,
                         cudaFuncAttributeMaxDynamicSharedMemorySize, O_SMEM);
    cudaFuncSetAttribute(attn_h,
                         cudaFuncAttributeMaxDynamicSharedMemorySize, ATT_SMEM);

    F2HArgs fa;
    fa.src[0] = q;   fa.dst[0] = xq;             fa.n[0] = B * LQ  * DM;
    fa.src[1] = kv;  fa.dst[1] = xkv;            fa.n[1] = B * LKV * DM;
    fa.src[2] = Wq;  fa.dst[2] = (__half*)p_wq;  fa.n[2] = DM * DM;
    fa.src[3] = Wk;  fa.dst[3] = (__half*)p_wk;  fa.n[3] = DM * DM;
    fa.src[4] = Wv;  fa.dst[4] = (__half*)p_wv;  fa.n[4] = DM * DM;
    fa.src[5] = Wo;  fa.dst[5] = (__half*)p_wo;  fa.n[5] = DM * DM;
    f2h_all<<<1024, 256>>>(fa);

    const dim3 blk(256);

    // QKV: 256-row m-tiles. grid.y = 8 (Q) + 32 (K) + 32 (V) = 72.
    gemm_qkv<<<dim3(DM / 128, 72), blk, QKV_SMEM>>>(
        xq, xkv, (__half*)p_wq, (__half*)p_wk, (__half*)p_wv,
        bq, bk, bv, (__half*)p_Q, (__half*)p_K, (__half*)p_V);

    attn_h<<<dim3(LQ / 128, B * NH), blk, ATT_SMEM>>>(
        (__half*)p_Q, (__half*)p_K, (__half*)p_V, ctx);

    gemm_o<<<dim3(DM / 128, (B * LQ) / 128), blk, O_SMEM>>>(
        ctx, (__half*)p_wo, bo, out);
}

// round 15
// speedup vs baseline: 1.1241x; 1.0495x over previous
#include <cuda_runtime.h>
#include <cuda_fp16.h>
#include <mma.h>
#include <cstdint>

using namespace nvcuda;

namespace cfg {
constexpr int DM  = 1024;
constexpr int NH  = 16;
constexpr int HD  = 64;
constexpr int B   = 4;
constexpr int LQ  = 512;
constexpr int LKV = 2048;
constexpr int LDH = 72;    // half leading dim (64+8): 144B rows, LDSM conflict-free
constexpr int LDE = 132;   // gemm epilogue fp32 staging leading dim
}

// -------- half scratch (inputs pre-converted once) -------------------------
__device__ __half g_xq [(size_t)cfg::B * cfg::LQ  * cfg::DM];
__device__ __half g_xkv[(size_t)cfg::B * cfg::LKV * cfg::DM];
__device__ __half g_wq [(size_t)cfg::DM * cfg::DM];
__device__ __half g_wk [(size_t)cfg::DM * cfg::DM];
__device__ __half g_wv [(size_t)cfg::DM * cfg::DM];
__device__ __half g_wo [(size_t)cfg::DM * cfg::DM];
__device__ __half g_Qh [(size_t)cfg::B * cfg::NH * cfg::LQ  * cfg::HD];
__device__ __half g_Kh [(size_t)cfg::B * cfg::NH * cfg::LKV * cfg::HD];
__device__ __half g_Vh [(size_t)cfg::B * cfg::NH * cfg::LKV * cfg::HD];
__device__ __half g_ctx[(size_t)cfg::B * cfg::LQ * cfg::DM];

__device__ __forceinline__ uint32_t smem_u32(const void* p) {
    uint32_t a;
    asm("{ .reg .u64 t; cvta.to.shared.u64 t, %1; cvt.u32.u64 %0, t; }"
        : "=r"(a) : "l"(p));
    return a;
}
#define CP_ASYNC16(dst_u32, src_ptr) \
    asm volatile("cp.async.cg.shared.global [%0], [%1], 16;" \
                 :: "r"(dst_u32), "l"(src_ptr) : "memory")
#define CP_ASYNC_COMMIT() asm volatile("cp.async.commit_group;" ::: "memory")
#define CP_ASYNC_WAIT0()  asm volatile("cp.async.wait_group 0;" ::: "memory")
#define CP_ASYNC_WAIT1()  asm volatile("cp.async.wait_group 1;" ::: "memory")

__device__ __forceinline__ void ldsm_x4(uint32_t& r0, uint32_t& r1,
                                        uint32_t& r2, uint32_t& r3, uint32_t addr) {
    asm volatile("ldmatrix.sync.aligned.m8n8.x4.shared.b16 {%0,%1,%2,%3}, [%4];"
                 : "=r"(r0), "=r"(r1), "=r"(r2), "=r"(r3) : "r"(addr));
}
__device__ __forceinline__ void ldsm_x4_t(uint32_t& r0, uint32_t& r1,
                                          uint32_t& r2, uint32_t& r3, uint32_t addr) {
    asm volatile("ldmatrix.sync.aligned.m8n8.x4.trans.shared.b16 {%0,%1,%2,%3}, [%4];"
                 : "=r"(r0), "=r"(r1), "=r"(r2), "=r"(r3) : "r"(addr));
}
__device__ __forceinline__ void mma16816(float* d, const uint32_t* a,
                                         uint32_t b0, uint32_t b1) {
    asm volatile(
        "mma.sync.aligned.m16n8k16.row.col.f32.f16.f16.f32 "
        "{%0,%1,%2,%3}, {%4,%5,%6,%7}, {%8,%9}, {%0,%1,%2,%3};"
        : "+f"(d[0]), "+f"(d[1]), "+f"(d[2]), "+f"(d[3])
        : "r"(a[0]), "r"(a[1]), "r"(a[2]), "r"(a[3]), "r"(b0), "r"(b1));
}
// 2^x on a packed half2 (one MUFU op for two values).
__device__ __forceinline__ uint32_t ex2_h2(uint32_t x) {
    uint32_t r;
    asm("ex2.approx.f16x2 %0, %1;" : "=r"(r) : "r"(x));
    return r;
}

// ---------------------------------------------------------------------------
// fp32 -> fp16 bulk convert, all six tensors in one launch.
// ---------------------------------------------------------------------------
struct F2HArgs {
    const float* src[6];
    __half*      dst[6];
    int          n[6];
};
__global__ void f2h_all(F2HArgs p)
{
#pragma unroll
    for (int seg = 0; seg < 6; seg++) {
        const float* a = p.src[seg];
        __half*      b = p.dst[seg];
        const int    n = p.n[seg];
        int i = (blockIdx.x * blockDim.x + threadIdx.x) * 4;
        int stride = gridDim.x * blockDim.x * 4;
        for (; i < n; i += stride) {
            float4 v = *reinterpret_cast<const float4*>(a + i);
            __half2 h0 = __floats2half2_rn(v.x, v.y);
            __half2 h1 = __floats2half2_rn(v.z, v.w);
            uint2 u;
            u.x = *reinterpret_cast<uint32_t*>(&h0);
            u.y = *reinterpret_cast<uint32_t*>(&h1);
            *reinterpret_cast<uint2*>(b + i) = u;
        }
    }
}

// ---------------------------------------------------------------------------
// Shared GEMM body (exact R11): Y = X @ W^T + bias, 128x128 tile, 8 warps
// (warp 32x64), K-chunk 64, 2-stage cp.async.
// ---------------------------------------------------------------------------
template <bool OUT_HALF>
__device__ __forceinline__ void gemm_body(
    const __half* __restrict__ X, const __half* __restrict__ W,
    const float* __restrict__ bias, void* __restrict__ Yv,
    int m0, int n0, int seq, float scale, __half* smh)
{
    using namespace cfg;
    constexpr int KC = 64, NCH = DM / KC;
    __half* bx[2] = { smh,                smh + 2 * 128 * LDH };
    __half* bw[2] = { smh + 128 * LDH,    smh + 3 * 128 * LDH };
    const uint32_t bxa[2] = { smem_u32(bx[0]), smem_u32(bx[1]) };
    const uint32_t bwa[2] = { smem_u32(bw[0]), smem_u32(bw[1]) };

    const int tid  = threadIdx.x;
    const int warp = tid >> 5;
    const int wr   = warp >> 1;
    const int wc   = warp & 1;

    wmma::fragment<wmma::accumulator, 16, 16, 16, float> acc[2][4];
#pragma unroll
    for (int i = 0; i < 2; i++)
#pragma unroll
        for (int j = 0; j < 4; j++) wmma::fill_fragment(acc[i][j], 0.0f);

    auto stage = [&](int s, int k0) {
#pragma unroll
        for (int i = 0; i < 4; i++) {
            int f = i * 256 + tid;
            int r = f >> 3, c8 = (f & 7) * 8;
            CP_ASYNC16(bxa[s] + (uint32_t)(r * LDH + c8) * 2,
                       X + (size_t)(m0 + r) * DM + k0 + c8);
            CP_ASYNC16(bwa[s] + (uint32_t)(r * LDH + c8) * 2,
                       W + (size_t)(n0 + r) * DM + k0 + c8);
        }
        CP_ASYNC_COMMIT();
    };

    stage(0, 0);
    for (int kc = 0; kc < NCH; kc++) {
        const int s = kc & 1;
        if (kc + 1 < NCH) { stage(1 - s, (kc + 1) * KC); CP_ASYNC_WAIT1(); }
        else              { CP_ASYNC_WAIT0(); }
        __syncthreads();
#pragma unroll
        for (int kk = 0; kk < KC; kk += 16) {
            wmma::fragment<wmma::matrix_a, 16, 16, 16, __half, wmma::row_major> a[2];
#pragma unroll
            for (int i = 0; i < 2; i++)
                wmma::load_matrix_sync(a[i], bx[s] + (wr * 32 + i * 16) * LDH + kk, LDH);
#pragma unroll
            for (int j = 0; j < 4; j++) {
                wmma::fragment<wmma::matrix_b, 16, 16, 16, __half, wmma::col_major> bf;
                wmma::load_matrix_sync(bf, bw[s] + (wc * 64 + j * 16) * LDH + kk, LDH);
#pragma unroll
                for (int i = 0; i < 2; i++)
                    wmma::mma_sync(acc[i][j], a[i], bf, acc[i][j]);
            }
        }
        __syncthreads();
    }

    float* stf = reinterpret_cast<float*>(smh);
#pragma unroll
    for (int i = 0; i < 2; i++)
#pragma unroll
        for (int j = 0; j < 4; j++)
            wmma::store_matrix_sync(stf + (wr * 32 + i * 16) * LDE + wc * 64 + j * 16,
                                    acc[i][j], LDE, wmma::mem_row_major);
    __syncthreads();
#pragma unroll
    for (int i = 0; i < 16; i++) {
        int f = i * 256 + tid;
        int r = f >> 5, c = (f & 31) << 2;
        float4 v  = *reinterpret_cast<float4*>(stf + r * LDE + c);
        float4 bv = *reinterpret_cast<const float4*>(bias + n0 + c);
        v.x += bv.x; v.y += bv.y; v.z += bv.z; v.w += bv.w;
        if (!OUT_HALF) {
            *reinterpret_cast<float4*>((float*)Yv + (size_t)(m0 + r) * DM + n0 + c) = v;
        } else {
            __half2 h0 = __floats2half2_rn(v.x * scale, v.y * scale);
            __half2 h1 = __floats2half2_rn(v.z * scale, v.w * scale);
            uint2 u;
            u.x = *reinterpret_cast<uint32_t*>(&h0);
            u.y = *reinterpret_cast<uint32_t*>(&h1);
            int h    = (n0 + c) >> 6;
            int bidx = (m0 + r) / seq;
            int l    = (m0 + r) % seq;
            *reinterpret_cast<uint2*>((__half*)Yv +
                (((size_t)(bidx * NH + h) * seq + l) << 6) + (c & 63)) = u;
        }
    }
}

// QKV (exact R11 config): grid.y = 16 (Q) + 64 (K) + 64 (V) = 144.
// Q scale = 0.125 * log2(e): S accumulates in the log2 domain for ex2-softmax.
__global__ __launch_bounds__(256, 2) void gemm_qkv(
    const __half* __restrict__ xq, const __half* __restrict__ xkv,
    const __half* __restrict__ wq, const __half* __restrict__ wk,
    const __half* __restrict__ wv,
    const float* __restrict__ bq, const float* __restrict__ bk,
    const float* __restrict__ bv,
    __half* __restrict__ Qh, __half* __restrict__ Kh, __half* __restrict__ Vh)
{
    using namespace cfg;
    extern __shared__ __half smh[];
    const int ty = blockIdx.y;
    const int n0 = blockIdx.x * 128;

    const __half *X, *W; const float* bias; __half* Y;
    int seq, m0; float scale;
    if (ty < 16)      { X = xq;  W = wq; bias = bq; Y = Qh; seq = LQ;  scale = 0.125f * 1.44269504f; m0 = ty * 128; }
    else if (ty < 80) { X = xkv; W = wk; bias = bk; Y = Kh; seq = LKV; scale = 1.0f;   m0 = (ty - 16) * 128; }
    else              { X = xkv; W = wv; bias = bv; Y = Vh; seq = LKV; scale = 1.0f;   m0 = (ty - 80) * 128; }

    gemm_body<true>(X, W, bias, Y, m0, n0, seq, scale, smh);
}

__global__ __launch_bounds__(256, 2) void gemm_o(
    const __half* __restrict__ X, const __half* __restrict__ W,
    const float* __restrict__ bias, float* __restrict__ Y)
{
    using namespace cfg;
    extern __shared__ __half smh[];
    gemm_body<false>(X, W, bias, Y, blockIdx.y * 128, blockIdx.x * 128,
                     0, 1.0f, smh);
}

// ---------------------------------------------------------------------------
// Attention v4: register-resident softmax, MUFU-halved.
//  - S accumulates log2-domain scores (Q pre-scaled by 0.125*log2e).
//  - P = ex2.approx.f16x2( half2(S) )  -> one MUFU op per 2 elements, result
//    is directly the PV A-fragment.
//  - Row sums via ones-column MMA (B-frag 1.0 in col 0) into persistent lacc:
//    removes the entire cvt/add/shuffle rowsum chain.
// ---------------------------------------------------------------------------
__global__ __launch_bounds__(256, 2) void attn_h(
    const __half* __restrict__ Qg, const __half* __restrict__ Kg,
    const __half* __restrict__ Vg, __half* __restrict__ ctx)
{
    using namespace cfg;
    extern __shared__ char smb[];
    __half* sQ    = (__half*)(smb);                                   // 128*72*2
    __half* sK[2] = { (__half*)(smb + 18432), (__half*)(smb + 27648) }; // 64*72*2
    __half* sV[2] = { (__half*)(smb + 36864), (__half*)(smb + 46080) };
    const uint32_t sQa = smem_u32(sQ);
    const uint32_t sKa[2] = { smem_u32(sK[0]), smem_u32(sK[1]) };
    const uint32_t sVa[2] = { smem_u32(sV[0]), smem_u32(sV[1]) };

    const int tid  = threadIdx.x;
    const int warp = tid >> 5;
    const int lane = tid & 31;
    const int bh   = blockIdx.y;
    const int q0   = blockIdx.x * 128;

    const __half* Q = Qg + (size_t)bh * LQ  * HD;
    const __half* K = Kg + (size_t)bh * LKV * HD;
    const __half* V = Vg + (size_t)bh * LKV * HD;

    const int grp = lane >> 3, li = lane & 7;
    const int krow = ((grp >> 1) << 3) + li, kcol = (grp & 1) << 3;
    const int vrow = ((grp & 1) << 3) + li, vcol = (grp >> 1) << 3;

    // Ones B-fragment for rowsum MMA: col 0 of an n8 tile = 1.0 (lanes 0-3
    // hold col 0's k-pairs in the m16n8k16 B layout).
    const uint32_t onesb = (lane < 4) ? 0x3C003C00u : 0u;

    auto stage_kv = [&](int s, int kc) {
#pragma unroll
        for (int i = 0; i < 2; i++) {
            int f = i * 256 + tid;
            int r = f >> 3, c8 = (f & 7) * 8;
            CP_ASYNC16(sKa[s] + (uint32_t)(r * LDH + c8) * 2,
                       K + (size_t)(kc * 64 + r) * HD + c8);
            CP_ASYNC16(sVa[s] + (uint32_t)(r * LDH + c8) * 2,
                       V + (size_t)(kc * 64 + r) * HD + c8);
        }
        CP_ASYNC_COMMIT();
    };

#pragma unroll
    for (int i = 0; i < 4; i++) {
        int f = i * 256 + tid;
        int r = f >> 3, c8 = (f & 7) * 8;
        CP_ASYNC16(sQa + (uint32_t)(r * LDH + c8) * 2,
                   Q + (size_t)(q0 + r) * HD + c8);
    }
    stage_kv(0, 0);

    uint32_t qa[4][4];
    float oacc[8][4];
#pragma unroll
    for (int j = 0; j < 8; j++)
#pragma unroll
        for (int t = 0; t < 4; t++) oacc[j][t] = 0.0f;
    float lacc[4] = {0.0f, 0.0f, 0.0f, 0.0f};   // rowsum accumulator (col 0)

    for (int kc = 0; kc < LKV / 64; kc++) {
        const int s = kc & 1;
        if (kc + 1 < LKV / 64) { stage_kv(1 - s, kc + 1); CP_ASYNC_WAIT1(); }
        else                   { CP_ASYNC_WAIT0(); }
        __syncthreads();

        if (kc == 0) {
#pragma unroll
            for (int ks = 0; ks < 4; ks++)
                ldsm_x4(qa[ks][0], qa[ks][1], qa[ks][2], qa[ks][3],
                        sQa + (uint32_t)((warp * 16 + vrow) * LDH + ks * 16 + vcol) * 2);
        }

        // ---- S(log2) = Qs @ K^T : 8 n8-tiles, fp32 acc in registers ----
        float sc[8][4];
#pragma unroll
        for (int j = 0; j < 8; j++)
#pragma unroll
            for (int t = 0; t < 4; t++) sc[j][t] = 0.0f;
#pragma unroll
        for (int ks = 0; ks < 4; ks++) {
#pragma unroll
            for (int jt = 0; jt < 4; jt++) {
                uint32_t b0, b1, b2, b3;
                ldsm_x4(b0, b1, b2, b3,
                        sKa[s] + (uint32_t)((jt * 16 + krow) * LDH + ks * 16 + kcol) * 2);
                mma16816(sc[2 * jt],     qa[ks], b0, b1);
                mma16816(sc[2 * jt + 1], qa[ks], b2, b3);
            }
        }

        // ---- P = 2^S via ex2.approx.f16x2, packed directly into A-frags ----
        uint32_t pa[4][4];
#pragma unroll
        for (int J = 0; J < 4; J++) {
            float* e0 = sc[2 * J];
            float* e1 = sc[2 * J + 1];
            __half2 x00 = __floats2half2_rn(e0[0], e0[1]);  // row r
            __half2 x01 = __floats2half2_rn(e0[2], e0[3]);  // row r+8
            __half2 x10 = __floats2half2_rn(e1[0], e1[1]);
            __half2 x11 = __floats2half2_rn(e1[2], e1[3]);
            pa[J][0] = ex2_h2(*reinterpret_cast<uint32_t*>(&x00));
            pa[J][1] = ex2_h2(*reinterpret_cast<uint32_t*>(&x01));
            pa[J][2] = ex2_h2(*reinterpret_cast<uint32_t*>(&x10));
            pa[J][3] = ex2_h2(*reinterpret_cast<uint32_t*>(&x11));
        }

        // ---- O += P @ V  and  rowsum += P @ ones ----
#pragma unroll
        for (int J = 0; J < 4; J++) {
#pragma unroll
            for (int dt = 0; dt < 4; dt++) {
                uint32_t b0, b1, b2, b3;
                ldsm_x4_t(b0, b1, b2, b3,
                          sVa[s] + (uint32_t)((J * 16 + vrow) * LDH + dt * 16 + vcol) * 2);
                mma16816(oacc[2 * dt],     pa[J], b0, b1);
                mma16816(oacc[2 * dt + 1], pa[J], b2, b3);
            }
            mma16816(lacc, pa[J], onesb, onesb);
        }
        __syncthreads();
    }

    // ---- broadcast row sums (held in quad-lane 0, col 0) and write O ----
    const float rsA = __shfl_sync(0xffffffffu, lacc[0], lane & 28);
    const float rsB = __shfl_sync(0xffffffffu, lacc[2], lane & 28);
    const float i0 = 1.0f / rsA, i1 = 1.0f / rsB;

    const int b  = bh / NH, hh = bh % NH;
    const int r0 = q0 + warp * 16 + (lane >> 2);
    const int cb = (lane & 3) * 2;
#pragma unroll
    for (int j = 0; j < 8; j++) {
        __half2 h0 = __floats2half2_rn(oacc[j][0] * i0, oacc[j][1] * i0);
        __half2 h1 = __floats2half2_rn(oacc[j][2] * i1, oacc[j][3] * i1);
        *reinterpret_cast<__half2*>(ctx +
            (((size_t)(b * LQ + r0) * NH + hh) << 6) + 8 * j + cb) = h0;
        *reinterpret_cast<__half2*>(ctx +
            (((size_t)(b * LQ + r0 + 8) * NH + hh) << 6) + 8 * j + cb) = h1;
    }
}

// ---------------------------------------------------------------------------
extern "C" void kernel_launch(void* const* d_in, const int* in_sizes, int n_in,
                              void* d_out, int out_size)
{
    using namespace cfg;
    (void)in_sizes; (void)n_in; (void)out_size;

    const float* q  = (const float*)d_in[0];
    const float* kv = (const float*)d_in[1];
    const float* Wq = (const float*)d_in[2];
    const float* bq = (const float*)d_in[3];
    const float* Wk = (const float*)d_in[4];
    const float* bk = (const float*)d_in[5];
    const float* Wv = (const float*)d_in[6];
    const float* bv = (const float*)d_in[7];
    const float* Wo = (const float*)d_in[8];
    const float* bo = (const float*)d_in[9];
    float* out = (float*)d_out;

    void *p_xq, *p_xkv, *p_wq, *p_wk, *p_wv, *p_wo, *p_Q, *p_K, *p_V, *p_ctx;
    cudaGetSymbolAddress(&p_xq,  g_xq);
    cudaGetSymbolAddress(&p_xkv, g_xkv);
    cudaGetSymbolAddress(&p_wq,  g_wq);
    cudaGetSymbolAddress(&p_wk,  g_wk);
    cudaGetSymbolAddress(&p_wv,  g_wv);
    cudaGetSymbolAddress(&p_wo,  g_wo);
    cudaGetSymbolAddress(&p_Q,   g_Qh);
    cudaGetSymbolAddress(&p_K,   g_Kh);
    cudaGetSymbolAddress(&p_V,   g_Vh);
    cudaGetSymbolAddress(&p_ctx, g_ctx);
    __half* xq  = (__half*)p_xq;
    __half* xkv = (__half*)p_xkv;
    __half* ctx = (__half*)p_ctx;

    const int GEMM_SMEM = 4 * 128 * LDH * 2;   // 73728 B
    const int ATT_SMEM  = 55296;               // sQ + 2x(64-row K,V)
    cudaFuncSetAttribute(gemm_qkv,
                         cudaFuncAttributeMaxDynamicSharedMemorySize, GEMM_SMEM);
    cudaFuncSetAttribute(gemm_o,
                         cudaFuncAttributeMaxDynamicSharedMemorySize, GEMM_SMEM);
    cudaFuncSetAttribute(attn_h,
                         cudaFuncAttributeMaxDynamicSharedMemorySize, ATT_SMEM);

    F2HArgs fa;
    fa.src[0] = q;   fa.dst[0] = xq;             fa.n[0] = B * LQ  * DM;
    fa.src[1] = kv;  fa.dst[1] = xkv;            fa.n[1] = B * LKV * DM;
    fa.src[2] = Wq;  fa.dst[2] = (__half*)p_wq;  fa.n[2] = DM * DM;
    fa.src[3] = Wk;  fa.dst[3] = (__half*)p_wk;  fa.n[3] = DM * DM;
    fa.src[4] = Wv;  fa.dst[4] = (__half*)p_wv;  fa.n[4] = DM * DM;
    fa.src[5] = Wo;  fa.dst[5] = (__half*)p_wo;  fa.n[5] = DM * DM;
    f2h_all<<<1024, 256>>>(fa);

    const dim3 blk(256);

    gemm_qkv<<<dim3(DM / 128, 144), blk, GEMM_SMEM>>>(
        xq, xkv, (__half*)p_wq, (__half*)p_wk, (__half*)p_wv,
        bq, bk, bv, (__half*)p_Q, (__half*)p_K, (__half*)p_V);

    attn_h<<<dim3(LQ / 128, B * NH), blk, ATT_SMEM>>>(
        (__half*)p_Q, (__half*)p_K, (__half*)p_V, ctx);

    gemm_o<<<dim3(DM / 128, (B * LQ) / 128), blk, GEMM_SMEM>>>(
        ctx, (__half*)p_wo, bo, out);
}